// round 14
// baseline (speedup 1.0000x reference)
#include <cuda_runtime.h>
#include <cuda_fp16.h>
#include <math.h>
#include <stdint.h>

// Problem constants
#define TT 8192
#define HH 2048
#define II 4096
#define EE 8
#define NSLOT (TT * 2)
#define MT 128
#define MAXTILES ((NSLOT / MT) + EE)   // 136

// GEMM tiling: block 128(M) x 128(B-rows), 512 threads, warps 4x4, warp 32x32
// 3-stage smem = 96KB -> 2 CTAs/SM: 32 warps in TWO barrier domains.
#define NTHREADS 512
#define KC 64                 // k elements per stage (128B rows fp16)
#define ASTG 16384            // A stage bytes: 128*128
#define BSTG 16384            // B stage bytes: 128*128
#define STG  (ASTG + BSTG)    // 32768
#define NSTAGE 3
#define SMEM_BYTES (NSTAGE * STG)   // 98304
#define NKC1 (HH / KC)        // 32
#define NKC2 (II / KC)        // 64

#define CVT_BLOCKS (TT * HH / 4 / 256)   // 16384
#define RTR_BLOCKS (TT / 8)              // 1024

// ----------------------------------------------------------------------------
// Scratch (device globals only)
// ----------------------------------------------------------------------------
__device__ int   g_tok_e[NSLOT];
__device__ float g_tok_w[NSLOT];
__device__ int   g_perm_tok[NSLOT];
__device__ float g_perm_w[NSLOT];
__device__ int   g_slot_of[NSLOT];
__device__ int   g_ntiles;
__device__ int   g_tile_e[MAXTILES];
__device__ int   g_tile_row0[MAXTILES];
__device__ int   g_tile_rows[MAXTILES];

__device__ __half g_hs16[(size_t)TT * HH];               // 32 MB
__device__ __half g_ws16[(size_t)EE * 2 * II * HH];      // 256 MB
__device__ __half g_w2s16[(size_t)EE * HH * II];         // 128 MB
__device__ __half g_act[(size_t)NSLOT * II];             // 128 MB
__device__ __half g_down16[(size_t)NSLOT * HH];          // 64 MB

// ----------------------------------------------------------------------------
// PTX helpers
// ----------------------------------------------------------------------------
__device__ __forceinline__ void cpasync16(uint32_t dst, const void* src) {
    asm volatile("cp.async.cg.shared.global [%0], [%1], 16;" :: "r"(dst), "l"(src));
}
__device__ __forceinline__ void cp_commit() {
    asm volatile("cp.async.commit_group;");
}
template <int N>
__device__ __forceinline__ void cp_wait() {
    asm volatile("cp.async.wait_group %0;" :: "n"(N));
}
__device__ __forceinline__ void ldsm4(uint32_t& r0, uint32_t& r1, uint32_t& r2,
                                      uint32_t& r3, uint32_t addr) {
    asm volatile("ldmatrix.sync.aligned.m8n8.x4.shared.b16 {%0,%1,%2,%3}, [%4];"
                 : "=r"(r0), "=r"(r1), "=r"(r2), "=r"(r3) : "r"(addr));
}
__device__ __forceinline__ void mma16816(float* c, const uint32_t* a, const uint32_t* b) {
    asm volatile(
        "mma.sync.aligned.m16n8k16.row.col.f32.f16.f16.f32 "
        "{%0,%1,%2,%3}, {%4,%5,%6,%7}, {%8,%9}, {%0,%1,%2,%3};\n"
        : "+f"(c[0]), "+f"(c[1]), "+f"(c[2]), "+f"(c[3])
        : "r"(a[0]), "r"(a[1]), "r"(a[2]), "r"(a[3]), "r"(b[0]), "r"(b[1]));
}
__device__ __forceinline__ uint2 cvt4(float4 v) {
    __half2 h0 = __floats2half2_rn(v.x, v.y);
    __half2 h1 = __floats2half2_rn(v.z, v.w);
    uint2 u;
    u.x = *(const uint32_t*)&h0;
    u.y = *(const uint32_t*)&h1;
    return u;
}

// ----------------------------------------------------------------------------
// Fused: blocks [0, CVT_BLOCKS) convert hidden fp32->fp16;
//        blocks [CVT_BLOCKS, +RTR_BLOCKS) run the router (float4 loads).
// ----------------------------------------------------------------------------
__global__ void fused_cvt_router(const float4* __restrict__ hs4,
                                 uint2* __restrict__ hs16,
                                 const float4* __restrict__ rw4) {
    if (blockIdx.x < CVT_BLOCKS) {
        int i = blockIdx.x * blockDim.x + threadIdx.x;
        hs16[i] = cvt4(hs4[i]);
        return;
    }
    int rb = blockIdx.x - CVT_BLOCKS;
    int token = rb * 8 + (threadIdx.x >> 5);
    int lane = threadIdx.x & 31;
    const float4* x4 = hs4 + (size_t)token * (HH / 4);
    float acc[EE];
#pragma unroll
    for (int e = 0; e < EE; e++) acc[e] = 0.f;
    for (int i = lane; i < HH / 4; i += 32) {
        float4 xv = x4[i];
#pragma unroll
        for (int e = 0; e < EE; e++) {
            float4 wv = rw4[e * (HH / 4) + i];
            acc[e] += xv.x * wv.x + xv.y * wv.y + xv.z * wv.z + xv.w * wv.w;
        }
    }
#pragma unroll
    for (int e = 0; e < EE; e++) {
#pragma unroll
        for (int o = 16; o > 0; o >>= 1)
            acc[e] += __shfl_xor_sync(0xffffffffu, acc[e], o);
    }
    if (lane == 0) {
        int i0 = 0; float v0 = acc[0];
#pragma unroll
        for (int e = 1; e < EE; e++) if (acc[e] > v0) { v0 = acc[e]; i0 = e; }
        int i1 = -1; float v1 = -1e30f;
#pragma unroll
        for (int e = 0; e < EE; e++) if (e != i0 && acc[e] > v1) { v1 = acc[e]; i1 = e; }
        float p1 = __expf(v1 - v0);
        float s = 1.f + p1;
        g_tok_e[token * 2 + 0] = i0;
        g_tok_e[token * 2 + 1] = i1;
        g_tok_w[token * 2 + 0] = 1.f / s;
        g_tok_w[token * 2 + 1] = p1 / s;
    }
}

// ----------------------------------------------------------------------------
// scan + scatter (one block, 1024 thr)
// ----------------------------------------------------------------------------
__global__ void scan_scatter_kernel() {
    __shared__ int s_cnt[EE];
    __shared__ int s_cur[EE];
    __shared__ int s_off[EE + 1];
    const int tid = threadIdx.x;
    const int lane = tid & 31;
    if (tid < EE) { s_cnt[tid] = 0; s_cur[tid] = 0; }
    __syncthreads();

    for (int i = tid; i < NSLOT; i += blockDim.x) {
        int e = g_tok_e[i];
        unsigned m = __match_any_sync(0xffffffffu, e);
        int leader = __ffs(m) - 1;
        if (lane == leader) atomicAdd(&s_cnt[e], __popc(m));
    }
    __syncthreads();

    if (tid == 0) {
        int off = 0, nt = 0;
        for (int e = 0; e < EE; e++) {
            s_off[e] = off;
            int c = s_cnt[e];
            for (int r = 0; r < c; r += MT) {
                g_tile_e[nt] = e;
                g_tile_row0[nt] = off + r;
                int rem = c - r;
                g_tile_rows[nt] = rem < MT ? rem : MT;
                nt++;
            }
            off += c;
        }
        s_off[EE] = off;
        g_ntiles = nt;
    }
    __syncthreads();

    for (int i = tid; i < NSLOT; i += blockDim.x) {
        int e = g_tok_e[i];
        unsigned m = __match_any_sync(0xffffffffu, e);
        int leader = __ffs(m) - 1;
        int base = 0;
        if (lane == leader) base = atomicAdd(&s_cur[e], __popc(m));
        base = __shfl_sync(m, base, leader);
        int rank = __popc(m & ((1u << lane) - 1u));
        int slot = s_off[e] + base + rank;
        g_perm_tok[slot] = i >> 1;
        g_perm_w[slot]   = g_tok_w[i];
        g_slot_of[i]     = slot;
    }
}

__global__ void cvt_kernel(const float4* __restrict__ src, uint2* __restrict__ dst) {
    int i = blockIdx.x * blockDim.x + threadIdx.x;
    dst[i] = cvt4(src[i]);
}

// out[t] = down16[slot0] + down16[slot1]
__global__ void combine_kernel(float* __restrict__ out) {
    int i = blockIdx.x * blockDim.x + threadIdx.x;
    int t = i >> 9;
    int c = (i & 511) * 4;
    int s0 = g_slot_of[t * 2 + 0];
    int s1 = g_slot_of[t * 2 + 1];
    uint2 ua = *(const uint2*)&g_down16[(size_t)s0 * HH + c];
    uint2 ub = *(const uint2*)&g_down16[(size_t)s1 * HH + c];
    float2 a0 = __half22float2(*(const __half2*)&ua.x);
    float2 a1 = __half22float2(*(const __half2*)&ua.y);
    float2 b0 = __half22float2(*(const __half2*)&ub.x);
    float2 b1 = __half22float2(*(const __half2*)&ub.y);
    float4 r;
    r.x = a0.x + b0.x; r.y = a0.y + b0.y;
    r.z = a1.x + b1.x; r.w = a1.y + b1.y;
    *(float4*)&out[(size_t)t * HH + c] = r;
}

// ----------------------------------------------------------------------------
// Mainloop body macro-equivalent: one k-chunk with COMPILE-TIME stage offset.
// ----------------------------------------------------------------------------

// GEMM1: act = SwiGLU( gather(hs16) @ ws16[e].T )
// 512 threads (16 warps, 4x4), block 128 x 128 B-rows, warp 32x32, 2 CTAs/SM.
// k-loop restructured: outer step 3, inner unrolled -> stage offsets constant.
__global__ void __launch_bounds__(NTHREADS, 2)
gemm1_kernel(const __half* __restrict__ hs16, const __half* __restrict__ ws16) {
    const int tile = blockIdx.y;
    if (tile >= g_ntiles) return;
    const int e    = g_tile_e[tile];
    const int row0 = g_tile_row0[tile];
    const int rows = g_tile_rows[tile];
    const int cb   = blockIdx.x;        // 0..63 (64 out cols each)

    extern __shared__ __align__(1024) unsigned char smem[];
    const uint32_t smem_u32 = (uint32_t)__cvta_generic_to_shared(smem);
    __shared__ int s_tok[MT];

    const int tid = threadIdx.x;
    if (tid < MT) {
        int sl = row0 + tid;
        if (sl >= NSLOT) sl = NSLOT - 1;
        s_tok[tid] = g_perm_tok[sl];
    }
    __syncthreads();

    const int arow  = tid >> 2;
    const int acseg = (tid & 3) * 2;
    const __half* agp = hs16 + (size_t)s_tok[arow] * HH;
    const uint32_t aP = smem_u32 + arow * 128 + ((arow & 7) << 4);
    const int brow  = tid >> 2;
    const int bcseg = (tid & 3) * 2;
    const int wrow = (brow & 1) ? (II + cb * 64 + (brow >> 1))
                                : (cb * 64 + (brow >> 1));
    const __half* bgp = ws16 + (size_t)e * (2 * (size_t)II) * HH + (size_t)wrow * HH;
    const uint32_t bP = smem_u32 + ASTG + brow * 128 + ((brow & 7) << 4);

    auto load_stage = [&](int kc, uint32_t so) {
        const __half* ag = agp + kc * KC;
        const __half* bg = bgp + kc * KC;
#pragma unroll
        for (int j = 0; j < 2; j++)
            cpasync16((aP ^ ((acseg + j) << 4)) + so, ag + (acseg + j) * 8);
#pragma unroll
        for (int j = 0; j < 2; j++)
            cpasync16((bP ^ ((bcseg + j) << 4)) + so, bg + (bcseg + j) * 8);
    };

    const int lane = tid & 31;
    const int warp = tid >> 5;
    const int wm = warp >> 2, wn = warp & 3;
    const int g = lane >> 2, t4 = lane & 3;
    const int rowA = wm * 32 + (lane & 15);
    const uint32_t PAu = (smem_u32 + rowA * 128 + ((rowA & 7) << 4)) ^ ((lane >> 4) << 4);
    const int rowB = wn * 32 + (lane & 15);
    const uint32_t PBu = (smem_u32 + ASTG + rowB * 128 + ((rowB & 7) << 4)) ^ ((lane >> 4) << 4);

    float acc[2][4][4];
#pragma unroll
    for (int i = 0; i < 2; i++)
#pragma unroll
        for (int j = 0; j < 4; j++)
#pragma unroll
            for (int k = 0; k < 4; k++) acc[i][j][k] = 0.f;

    auto consume = [&](uint32_t so) {
#pragma unroll
        for (int ksi = 0; ksi < 4; ksi++) {
            const uint32_t kx = ksi << 5;
            uint32_t a[2][4];
#pragma unroll
            for (int mi = 0; mi < 2; mi++)
                ldsm4(a[mi][0], a[mi][1], a[mi][2], a[mi][3],
                      (PAu ^ kx) + so + mi * 2048);
            uint32_t b[4][2];
#pragma unroll
            for (int pr = 0; pr < 2; pr++) {
                uint32_t r0, r1, r2, r3;
                ldsm4(r0, r1, r2, r3, (PBu ^ kx) + so + pr * 2048);
                b[2 * pr + 0][0] = r0; b[2 * pr + 0][1] = r2;
                b[2 * pr + 1][0] = r1; b[2 * pr + 1][1] = r3;
            }
#pragma unroll
            for (int ni = 0; ni < 4; ni++)
#pragma unroll
                for (int mi = 0; mi < 2; mi++)
                    mma16816(acc[mi][ni], a[mi], b[ni]);
        }
    };

    load_stage(0, 0 * STG); cp_commit();
    load_stage(1, 1 * STG); cp_commit();

#pragma unroll 1
    for (int kb = 0; kb < NKC1; kb += NSTAGE) {
#pragma unroll
        for (int s = 0; s < NSTAGE; s++) {
            if (kb + s >= NKC1) break;
            cp_wait<1>();
            __syncthreads();
            const int kn = kb + s + 2;
            if (kn < NKC1) load_stage(kn, (uint32_t)(((s + 2) % NSTAGE) * STG));
            cp_commit();
            consume((uint32_t)(s * STG));
        }
    }
    __syncthreads();

    // epilogue: SwiGLU, stage in smem (128 x 64 fp16, pitch 72), coalesced store
    __half* stg = (__half*)smem;
    const int SP = 72;
#pragma unroll
    for (int mi = 0; mi < 2; mi++)
#pragma unroll
        for (int ni = 0; ni < 4; ni++)
#pragma unroll
            for (int rr = 0; rr < 2; rr++) {
                int m = wm * 32 + mi * 16 + g + rr * 8;
                int col = wn * 16 + ni * 4 + t4;
                float gate = acc[mi][ni][rr * 2 + 0];
                float up   = acc[mi][ni][rr * 2 + 1];
                float v = gate * up / (1.f + __expf(-gate));
                stg[m * SP + col] = __float2half_rn(v);
            }
    __syncthreads();
    {
        int r = tid >> 2, seg = tid & 3;
        if (r < rows) {
            const uint4* s = (const uint4*)&stg[r * SP + seg * 16];
            uint4* d = (uint4*)&g_act[(size_t)(row0 + r) * II + cb * 64 + seg * 16];
            d[0] = s[0];
            d[1] = s[1];
        }
    }
}

// ----------------------------------------------------------------------------
// GEMM2: g_down16 = w * ( act @ w2s16[e].T ).  Block 128 x 128 out cols, K=II.
// 2 CTAs per SM; same constant-offset k-loop.
// ----------------------------------------------------------------------------
__global__ void __launch_bounds__(NTHREADS, 2)
gemm2_kernel(const __half* __restrict__ act, const __half* __restrict__ w2s16) {
    const int tile = blockIdx.y;
    if (tile >= g_ntiles) return;
    const int e    = g_tile_e[tile];
    const int row0 = g_tile_row0[tile];
    const int rows = g_tile_rows[tile];
    const int n0   = blockIdx.x * 128;   // 0..15

    extern __shared__ __align__(1024) unsigned char smem[];
    const uint32_t smem_u32 = (uint32_t)__cvta_generic_to_shared(smem);
    __shared__ float s_w[MT];

    const int tid = threadIdx.x;
    if (tid < MT) {
        int sl = row0 + tid;
        if (sl >= NSLOT) sl = NSLOT - 1;
        s_w[tid] = g_perm_w[sl];
    }
    __syncthreads();

    const int arow  = tid >> 2;
    const int acseg = (tid & 3) * 2;
    int asl = row0 + arow;
    if (asl >= NSLOT) asl = NSLOT - 1;
    const __half* agp = act + (size_t)asl * II;
    const uint32_t aP = smem_u32 + arow * 128 + ((arow & 7) << 4);

    const int brow  = tid >> 2;
    const int bcseg = (tid & 3) * 2;
    const __half* bgp = w2s16 + (size_t)e * HH * II + (size_t)(n0 + brow) * II;
    const uint32_t bP = smem_u32 + ASTG + brow * 128 + ((brow & 7) << 4);

    auto load_stage = [&](int kc, uint32_t so) {
        const __half* ag = agp + kc * KC;
        const __half* bg = bgp + kc * KC;
#pragma unroll
        for (int j = 0; j < 2; j++)
            cpasync16((aP ^ ((acseg + j) << 4)) + so, ag + (acseg + j) * 8);
#pragma unroll
        for (int j = 0; j < 2; j++)
            cpasync16((bP ^ ((bcseg + j) << 4)) + so, bg + (bcseg + j) * 8);
    };

    const int lane = tid & 31;
    const int warp = tid >> 5;
    const int wm = warp >> 2, wn = warp & 3;
    const int g = lane >> 2, t4 = lane & 3;
    const int rowA = wm * 32 + (lane & 15);
    const uint32_t PAu = (smem_u32 + rowA * 128 + ((rowA & 7) << 4)) ^ ((lane >> 4) << 4);
    const int rowB = wn * 32 + (lane & 15);
    const uint32_t PBu = (smem_u32 + ASTG + rowB * 128 + ((rowB & 7) << 4)) ^ ((lane >> 4) << 4);

    float acc[2][4][4];
#pragma unroll
    for (int i = 0; i < 2; i++)
#pragma unroll
        for (int j = 0; j < 4; j++)
#pragma unroll
            for (int k = 0; k < 4; k++) acc[i][j][k] = 0.f;

    auto consume = [&](uint32_t so) {
#pragma unroll
        for (int ksi = 0; ksi < 4; ksi++) {
            const uint32_t kx = ksi << 5;
            uint32_t a[2][4];
#pragma unroll
            for (int mi = 0; mi < 2; mi++)
                ldsm4(a[mi][0], a[mi][1], a[mi][2], a[mi][3],
                      (PAu ^ kx) + so + mi * 2048);
            uint32_t b[4][2];
#pragma unroll
            for (int pr = 0; pr < 2; pr++) {
                uint32_t r0, r1, r2, r3;
                ldsm4(r0, r1, r2, r3, (PBu ^ kx) + so + pr * 2048);
                b[2 * pr + 0][0] = r0; b[2 * pr + 0][1] = r2;
                b[2 * pr + 1][0] = r1; b[2 * pr + 1][1] = r3;
            }
#pragma unroll
            for (int ni = 0; ni < 4; ni++)
#pragma unroll
                for (int mi = 0; mi < 2; mi++)
                    mma16816(acc[mi][ni], a[mi], b[ni]);
        }
    };

    load_stage(0, 0 * STG); cp_commit();
    load_stage(1, 1 * STG); cp_commit();

#pragma unroll 1
    for (int kb = 0; kb < NKC2; kb += NSTAGE) {
#pragma unroll
        for (int s = 0; s < NSTAGE; s++) {
            if (kb + s >= NKC2) break;
            cp_wait<1>();
            __syncthreads();
            const int kn = kb + s + 2;
            if (kn < NKC2) load_stage(kn, (uint32_t)(((s + 2) % NSTAGE) * STG));
            cp_commit();
            consume((uint32_t)(s * STG));
        }
    }

    // epilogue: scale by routing weight, fp16 stores (half2)
#pragma unroll
    for (int mi = 0; mi < 2; mi++)
#pragma unroll
        for (int ni = 0; ni < 4; ni++)
#pragma unroll
            for (int rr = 0; rr < 2; rr++) {
                int m = wm * 32 + mi * 16 + g + rr * 8;
                if (m < rows) {
                    int col = n0 + wn * 32 + ni * 8 + 2 * t4;
                    float w = s_w[m];
                    __half2 h = __floats2half2_rn(acc[mi][ni][rr * 2 + 0] * w,
                                                  acc[mi][ni][rr * 2 + 1] * w);
                    *(__half2*)&g_down16[(size_t)(row0 + m) * HH + col] = h;
                }
            }
}

// ----------------------------------------------------------------------------
// kernel_launch — creation order: fused(0), scan(1), cvt_ws(2), gemm1(3!),
// cvt_w2s(4), gemm2(5), combine(6).
// ----------------------------------------------------------------------------
extern "C" void kernel_launch(void* const* d_in, const int* in_sizes, int n_in,
                              void* d_out, int out_size) {
    const float* hs  = (const float*)d_in[0];
    const float* rw  = (const float*)d_in[1];
    const float* ws  = (const float*)d_in[2];
    const float* w2s = (const float*)d_in[3];
    float* out = (float*)d_out;
    (void)in_sizes; (void)n_in; (void)out_size;

    static cudaStream_t s2 = nullptr, s3 = nullptr;
    static cudaEvent_t evFork = nullptr, evJ1 = nullptr, evJ2 = nullptr;
    if (!s2) {
        cudaStreamCreateWithFlags(&s2, cudaStreamNonBlocking);
        cudaStreamCreateWithFlags(&s3, cudaStreamNonBlocking);
        cudaEventCreateWithFlags(&evFork, cudaEventDisableTiming);
        cudaEventCreateWithFlags(&evJ1, cudaEventDisableTiming);
        cudaEventCreateWithFlags(&evJ2, cudaEventDisableTiming);
    }

    cudaFuncSetAttribute(gemm1_kernel,
                         cudaFuncAttributeMaxDynamicSharedMemorySize, SMEM_BYTES);
    cudaFuncSetAttribute(gemm2_kernel,
                         cudaFuncAttributeMaxDynamicSharedMemorySize, SMEM_BYTES);

    __half* hs16  = nullptr; cudaGetSymbolAddress((void**)&hs16,  g_hs16);
    __half* ws16  = nullptr; cudaGetSymbolAddress((void**)&ws16,  g_ws16);
    __half* w2s16 = nullptr; cudaGetSymbolAddress((void**)&w2s16, g_w2s16);
    __half* act   = nullptr; cudaGetSymbolAddress((void**)&act,   g_act);

    // fork side streams at graph start (they read only raw inputs)
    cudaEventRecord(evFork, 0);
    cudaStreamWaitEvent(s2, evFork, 0);
    cudaStreamWaitEvent(s3, evFork, 0);

    // 0: fused hidden-cvt + router
    fused_cvt_router<<<CVT_BLOCKS + RTR_BLOCKS, 256>>>(
        (const float4*)hs, (uint2*)hs16, (const float4*)rw);
    // 1: scan + scatter
    scan_scatter_kernel<<<1, 1024>>>();
    // 2 (s2): ws fp32->fp16 (overlaps 0-1)
    cvt_kernel<<<(EE * 2 * II * (HH / 4)) / 256, 256, 0, s2>>>(
        (const float4*)ws, (uint2*)ws16);
    cudaEventRecord(evJ1, s2);
    cudaStreamWaitEvent(0, evJ1, 0);
    // 3: gemm1  (ncu capture slot)
    dim3 g1(II / 64, MAXTILES);                  // 64 x 136
    gemm1_kernel<<<g1, NTHREADS, SMEM_BYTES>>>(hs16, ws16);
    // 4 (s3): w2s fp32->fp16 (overlaps gemm1)
    cvt_kernel<<<(EE * HH * (II / 4)) / 256, 256, 0, s3>>>(
        (const float4*)w2s, (uint2*)w2s16);
    cudaEventRecord(evJ2, s3);
    cudaStreamWaitEvent(0, evJ2, 0);
    // 5: gemm2
    dim3 g2(HH / 128, MAXTILES);                 // 16 x 136
    gemm2_kernel<<<g2, NTHREADS, SMEM_BYTES>>>(act, w2s16);
    // 6: combine
    combine_kernel<<<(TT * (HH / 4)) / 256, 256>>>(out);
}

// round 15
// speedup vs baseline: 1.0266x; 1.0266x over previous
#include <cuda_runtime.h>
#include <cuda_fp16.h>
#include <math.h>
#include <stdint.h>

// Problem constants
#define TT 8192
#define HH 2048
#define II 4096
#define EE 8
#define NSLOT (TT * 2)
#define MT 128
#define MAXTILES ((NSLOT / MT) + EE)   // 136

// GEMM tiling (R13 proven-best): block 128(M) x 128(B-rows), 512 threads,
// warps 4x4, warp tile 32x32, 3-stage pipeline, 2 CTAs/SM (split barriers).
#define NTHREADS 512
#define KC 64                 // k elements per stage (128B rows fp16)
#define ASTG 16384            // A stage bytes: 128*128
#define BSTG 16384            // B stage bytes: 128*128
#define STG  (ASTG + BSTG)    // 32768
#define NSTAGE 3
#define SMEM_BYTES (NSTAGE * STG)   // 98304
#define NKC1 (HH / KC)        // 32
#define NKC2 (II / KC)        // 64

#define CVT_BLOCKS (TT * HH / 4 / 256)   // 16384
#define RTR_BLOCKS (TT / 8)              // 1024

// ----------------------------------------------------------------------------
// Scratch (device globals only)
// ----------------------------------------------------------------------------
__device__ int   g_tok_e[NSLOT];
__device__ float g_tok_w[NSLOT];
__device__ int   g_perm_tok[NSLOT];
__device__ float g_perm_w[NSLOT];
__device__ int   g_slot_of[NSLOT];
__device__ int   g_ntiles;
__device__ int   g_tile_e[MAXTILES];
__device__ int   g_tile_row0[MAXTILES];
__device__ int   g_tile_rows[MAXTILES];

__device__ __half g_hs16[(size_t)TT * HH];               // 32 MB
__device__ __half g_ws16[(size_t)EE * 2 * II * HH];      // 256 MB
__device__ __half g_w2s16[(size_t)EE * HH * II];         // 128 MB
__device__ __half g_act[(size_t)NSLOT * II];             // 128 MB
__device__ __half g_down16[(size_t)NSLOT * HH];          // 64 MB

// ----------------------------------------------------------------------------
// PTX helpers
// ----------------------------------------------------------------------------
__device__ __forceinline__ void cpasync16(uint32_t dst, const void* src) {
    asm volatile("cp.async.cg.shared.global [%0], [%1], 16;" :: "r"(dst), "l"(src));
}
__device__ __forceinline__ void cp_commit() {
    asm volatile("cp.async.commit_group;");
}
template <int N>
__device__ __forceinline__ void cp_wait() {
    asm volatile("cp.async.wait_group %0;" :: "n"(N));
}
__device__ __forceinline__ void ldsm4(uint32_t& r0, uint32_t& r1, uint32_t& r2,
                                      uint32_t& r3, uint32_t addr) {
    asm volatile("ldmatrix.sync.aligned.m8n8.x4.shared.b16 {%0,%1,%2,%3}, [%4];"
                 : "=r"(r0), "=r"(r1), "=r"(r2), "=r"(r3) : "r"(addr));
}
__device__ __forceinline__ void mma16816(float* c, const uint32_t* a, const uint32_t* b) {
    asm volatile(
        "mma.sync.aligned.m16n8k16.row.col.f32.f16.f16.f32 "
        "{%0,%1,%2,%3}, {%4,%5,%6,%7}, {%8,%9}, {%0,%1,%2,%3};\n"
        : "+f"(c[0]), "+f"(c[1]), "+f"(c[2]), "+f"(c[3])
        : "r"(a[0]), "r"(a[1]), "r"(a[2]), "r"(a[3]), "r"(b[0]), "r"(b[1]));
}
__device__ __forceinline__ uint2 cvt4(float4 v) {
    __half2 h0 = __floats2half2_rn(v.x, v.y);
    __half2 h1 = __floats2half2_rn(v.z, v.w);
    uint2 u;
    u.x = *(const uint32_t*)&h0;
    u.y = *(const uint32_t*)&h1;
    return u;
}

// ----------------------------------------------------------------------------
// Fused: blocks [0, CVT_BLOCKS) convert hidden fp32->fp16;
//        blocks [CVT_BLOCKS, +RTR_BLOCKS) run the router (float4 loads).
// ----------------------------------------------------------------------------
__global__ void fused_cvt_router(const float4* __restrict__ hs4,
                                 uint2* __restrict__ hs16,
                                 const float4* __restrict__ rw4) {
    if (blockIdx.x < CVT_BLOCKS) {
        int i = blockIdx.x * blockDim.x + threadIdx.x;
        hs16[i] = cvt4(hs4[i]);
        return;
    }
    int rb = blockIdx.x - CVT_BLOCKS;
    int token = rb * 8 + (threadIdx.x >> 5);
    int lane = threadIdx.x & 31;
    const float4* x4 = hs4 + (size_t)token * (HH / 4);
    float acc[EE];
#pragma unroll
    for (int e = 0; e < EE; e++) acc[e] = 0.f;
    for (int i = lane; i < HH / 4; i += 32) {
        float4 xv = x4[i];
#pragma unroll
        for (int e = 0; e < EE; e++) {
            float4 wv = rw4[e * (HH / 4) + i];
            acc[e] += xv.x * wv.x + xv.y * wv.y + xv.z * wv.z + xv.w * wv.w;
        }
    }
#pragma unroll
    for (int e = 0; e < EE; e++) {
#pragma unroll
        for (int o = 16; o > 0; o >>= 1)
            acc[e] += __shfl_xor_sync(0xffffffffu, acc[e], o);
    }
    if (lane == 0) {
        int i0 = 0; float v0 = acc[0];
#pragma unroll
        for (int e = 1; e < EE; e++) if (acc[e] > v0) { v0 = acc[e]; i0 = e; }
        int i1 = -1; float v1 = -1e30f;
#pragma unroll
        for (int e = 0; e < EE; e++) if (e != i0 && acc[e] > v1) { v1 = acc[e]; i1 = e; }
        float p1 = __expf(v1 - v0);
        float s = 1.f + p1;
        g_tok_e[token * 2 + 0] = i0;
        g_tok_e[token * 2 + 1] = i1;
        g_tok_w[token * 2 + 0] = 1.f / s;
        g_tok_w[token * 2 + 1] = p1 / s;
    }
}

// ----------------------------------------------------------------------------
// scan + scatter (one block, 1024 thr)
// ----------------------------------------------------------------------------
__global__ void scan_scatter_kernel() {
    __shared__ int s_cnt[EE];
    __shared__ int s_cur[EE];
    __shared__ int s_off[EE + 1];
    const int tid = threadIdx.x;
    const int lane = tid & 31;
    if (tid < EE) { s_cnt[tid] = 0; s_cur[tid] = 0; }
    __syncthreads();

    for (int i = tid; i < NSLOT; i += blockDim.x) {
        int e = g_tok_e[i];
        unsigned m = __match_any_sync(0xffffffffu, e);
        int leader = __ffs(m) - 1;
        if (lane == leader) atomicAdd(&s_cnt[e], __popc(m));
    }
    __syncthreads();

    if (tid == 0) {
        int off = 0, nt = 0;
        for (int e = 0; e < EE; e++) {
            s_off[e] = off;
            int c = s_cnt[e];
            for (int r = 0; r < c; r += MT) {
                g_tile_e[nt] = e;
                g_tile_row0[nt] = off + r;
                int rem = c - r;
                g_tile_rows[nt] = rem < MT ? rem : MT;
                nt++;
            }
            off += c;
        }
        s_off[EE] = off;
        g_ntiles = nt;
    }
    __syncthreads();

    for (int i = tid; i < NSLOT; i += blockDim.x) {
        int e = g_tok_e[i];
        unsigned m = __match_any_sync(0xffffffffu, e);
        int leader = __ffs(m) - 1;
        int base = 0;
        if (lane == leader) base = atomicAdd(&s_cur[e], __popc(m));
        base = __shfl_sync(m, base, leader);
        int rank = __popc(m & ((1u << lane) - 1u));
        int slot = s_off[e] + base + rank;
        g_perm_tok[slot] = i >> 1;
        g_perm_w[slot]   = g_tok_w[i];
        g_slot_of[i]     = slot;
    }
}

__global__ void cvt_kernel(const float4* __restrict__ src, uint2* __restrict__ dst) {
    int i = blockIdx.x * blockDim.x + threadIdx.x;
    dst[i] = cvt4(src[i]);
}

// out[t] = down16[slot0] + down16[slot1]; 8 floats per thread (16B loads)
__global__ void combine_kernel(float* __restrict__ out) {
    int i = blockIdx.x * blockDim.x + threadIdx.x;   // over T*H/8
    int t = i >> 8;               // H/8 = 256 groups per row
    int c = (i & 255) * 8;
    int s0 = g_slot_of[t * 2 + 0];
    int s1 = g_slot_of[t * 2 + 1];
    uint4 ua = *(const uint4*)&g_down16[(size_t)s0 * HH + c];
    uint4 ub = *(const uint4*)&g_down16[(size_t)s1 * HH + c];
    const __half2* ha = (const __half2*)&ua;
    const __half2* hb = (const __half2*)&ub;
    float4 r0, r1;
    {
        float2 a = __half22float2(ha[0]), b = __half22float2(hb[0]);
        r0.x = a.x + b.x; r0.y = a.y + b.y;
        a = __half22float2(ha[1]); b = __half22float2(hb[1]);
        r0.z = a.x + b.x; r0.w = a.y + b.y;
        a = __half22float2(ha[2]); b = __half22float2(hb[2]);
        r1.x = a.x + b.x; r1.y = a.y + b.y;
        a = __half22float2(ha[3]); b = __half22float2(hb[3]);
        r1.z = a.x + b.x; r1.w = a.y + b.y;
    }
    float* dst = &out[(size_t)t * HH + c];
    ((float4*)dst)[0] = r0;
    ((float4*)dst)[1] = r1;
}

// ----------------------------------------------------------------------------
// GEMM1: act = SwiGLU( gather(hs16) @ ws16[e].T )   (R13 verbatim mainloop)
// 512 threads (16 warps, 4x4), block 128 x 128 B-rows, warp 32x32, 2 CTAs/SM.
// ----------------------------------------------------------------------------
__global__ void __launch_bounds__(NTHREADS, 2)
gemm1_kernel(const __half* __restrict__ hs16, const __half* __restrict__ ws16) {
    const int tile = blockIdx.y;
    if (tile >= g_ntiles) return;
    const int e    = g_tile_e[tile];
    const int row0 = g_tile_row0[tile];
    const int rows = g_tile_rows[tile];
    const int cb   = blockIdx.x;        // 0..63 (64 out cols each)

    extern __shared__ __align__(1024) unsigned char smem[];
    const uint32_t smem_u32 = (uint32_t)__cvta_generic_to_shared(smem);
    __shared__ int s_tok[MT];

    const int tid = threadIdx.x;
    if (tid < MT) {
        int sl = row0 + tid;
        if (sl >= NSLOT) sl = NSLOT - 1;
        s_tok[tid] = g_perm_tok[sl];
    }
    __syncthreads();

    const int arow  = tid >> 2;
    const int acseg = (tid & 3) * 2;
    const __half* agp = hs16 + (size_t)s_tok[arow] * HH;
    const uint32_t aP = smem_u32 + arow * 128 + ((arow & 7) << 4);
    const int brow  = tid >> 2;
    const int bcseg = (tid & 3) * 2;
    const int wrow = (brow & 1) ? (II + cb * 64 + (brow >> 1))
                                : (cb * 64 + (brow >> 1));
    const __half* bgp = ws16 + (size_t)e * (2 * (size_t)II) * HH + (size_t)wrow * HH;
    const uint32_t bP = smem_u32 + ASTG + brow * 128 + ((brow & 7) << 4);

    auto load_stage = [&](int kc, int buf) {
        const uint32_t so = buf * STG;
        const __half* ag = agp + kc * KC;
        const __half* bg = bgp + kc * KC;
#pragma unroll
        for (int j = 0; j < 2; j++)
            cpasync16((aP ^ ((acseg + j) << 4)) + so, ag + (acseg + j) * 8);
#pragma unroll
        for (int j = 0; j < 2; j++)
            cpasync16((bP ^ ((bcseg + j) << 4)) + so, bg + (bcseg + j) * 8);
    };

    const int lane = tid & 31;
    const int warp = tid >> 5;
    const int wm = warp >> 2, wn = warp & 3;
    const int g = lane >> 2, t4 = lane & 3;
    const int rowA = wm * 32 + (lane & 15);
    const uint32_t PAu = (smem_u32 + rowA * 128 + ((rowA & 7) << 4)) ^ ((lane >> 4) << 4);
    const int rowB = wn * 32 + (lane & 15);
    const uint32_t PBu = (smem_u32 + ASTG + rowB * 128 + ((rowB & 7) << 4)) ^ ((lane >> 4) << 4);

    float acc[2][4][4];
#pragma unroll
    for (int i = 0; i < 2; i++)
#pragma unroll
        for (int j = 0; j < 4; j++)
#pragma unroll
            for (int k = 0; k < 4; k++) acc[i][j][k] = 0.f;

    load_stage(0, 0); cp_commit();
    load_stage(1, 1); cp_commit();

    for (int kc = 0; kc < NKC1; kc++) {
        cp_wait<1>();
        __syncthreads();
        if (kc + 2 < NKC1) load_stage(kc + 2, (kc + 2) % NSTAGE);
        cp_commit();

        const uint32_t so = (kc % NSTAGE) * STG;
#pragma unroll
        for (int ksi = 0; ksi < 4; ksi++) {
            const uint32_t kx = ksi << 5;
            uint32_t a[2][4];
#pragma unroll
            for (int mi = 0; mi < 2; mi++)
                ldsm4(a[mi][0], a[mi][1], a[mi][2], a[mi][3],
                      (PAu ^ kx) + so + mi * 2048);
            uint32_t b[4][2];
#pragma unroll
            for (int pr = 0; pr < 2; pr++) {
                uint32_t r0, r1, r2, r3;
                ldsm4(r0, r1, r2, r3, (PBu ^ kx) + so + pr * 2048);
                b[2 * pr + 0][0] = r0; b[2 * pr + 0][1] = r2;
                b[2 * pr + 1][0] = r1; b[2 * pr + 1][1] = r3;
            }
#pragma unroll
            for (int ni = 0; ni < 4; ni++)
#pragma unroll
                for (int mi = 0; mi < 2; mi++)
                    mma16816(acc[mi][ni], a[mi], b[ni]);
        }
    }
    __syncthreads();

    // epilogue: SwiGLU, stage in smem (128 x 64 fp16, pitch 72), coalesced store
    __half* stg = (__half*)smem;
    const int SP = 72;
#pragma unroll
    for (int mi = 0; mi < 2; mi++)
#pragma unroll
        for (int ni = 0; ni < 4; ni++)
#pragma unroll
            for (int rr = 0; rr < 2; rr++) {
                int m = wm * 32 + mi * 16 + g + rr * 8;
                int col = wn * 16 + ni * 4 + t4;
                float gate = acc[mi][ni][rr * 2 + 0];
                float up   = acc[mi][ni][rr * 2 + 1];
                float v = gate * up / (1.f + __expf(-gate));
                stg[m * SP + col] = __float2half_rn(v);
            }
    __syncthreads();
    {
        int r = tid >> 2, seg = tid & 3;
        if (r < rows) {
            const uint4* s = (const uint4*)&stg[r * SP + seg * 16];
            uint4* d = (uint4*)&g_act[(size_t)(row0 + r) * II + cb * 64 + seg * 16];
            d[0] = s[0];
            d[1] = s[1];
        }
    }
}

// ----------------------------------------------------------------------------
// GEMM2: g_down16 = w * ( act @ w2s16[e].T ).  Block 128 x 128 out cols, K=II.
// 2 CTAs per SM.  (R13 verbatim mainloop)
// ----------------------------------------------------------------------------
__global__ void __launch_bounds__(NTHREADS, 2)
gemm2_kernel(const __half* __restrict__ act, const __half* __restrict__ w2s16) {
    const int tile = blockIdx.y;
    if (tile >= g_ntiles) return;
    const int e    = g_tile_e[tile];
    const int row0 = g_tile_row0[tile];
    const int rows = g_tile_rows[tile];
    const int n0   = blockIdx.x * 128;   // 0..15

    extern __shared__ __align__(1024) unsigned char smem[];
    const uint32_t smem_u32 = (uint32_t)__cvta_generic_to_shared(smem);
    __shared__ float s_w[MT];

    const int tid = threadIdx.x;
    if (tid < MT) {
        int sl = row0 + tid;
        if (sl >= NSLOT) sl = NSLOT - 1;
        s_w[tid] = g_perm_w[sl];
    }
    __syncthreads();

    const int arow  = tid >> 2;
    const int acseg = (tid & 3) * 2;
    int asl = row0 + arow;
    if (asl >= NSLOT) asl = NSLOT - 1;
    const __half* agp = act + (size_t)asl * II;
    const uint32_t aP = smem_u32 + arow * 128 + ((arow & 7) << 4);

    const int brow  = tid >> 2;
    const int bcseg = (tid & 3) * 2;
    const __half* bgp = w2s16 + (size_t)e * HH * II + (size_t)(n0 + brow) * II;
    const uint32_t bP = smem_u32 + ASTG + brow * 128 + ((brow & 7) << 4);

    auto load_stage = [&](int kc, int buf) {
        const uint32_t so = buf * STG;
        const __half* ag = agp + kc * KC;
        const __half* bg = bgp + kc * KC;
#pragma unroll
        for (int j = 0; j < 2; j++)
            cpasync16((aP ^ ((acseg + j) << 4)) + so, ag + (acseg + j) * 8);
#pragma unroll
        for (int j = 0; j < 2; j++)
            cpasync16((bP ^ ((bcseg + j) << 4)) + so, bg + (bcseg + j) * 8);
    };

    const int lane = tid & 31;
    const int warp = tid >> 5;
    const int wm = warp >> 2, wn = warp & 3;
    const int g = lane >> 2, t4 = lane & 3;
    const int rowA = wm * 32 + (lane & 15);
    const uint32_t PAu = (smem_u32 + rowA * 128 + ((rowA & 7) << 4)) ^ ((lane >> 4) << 4);
    const int rowB = wn * 32 + (lane & 15);
    const uint32_t PBu = (smem_u32 + ASTG + rowB * 128 + ((rowB & 7) << 4)) ^ ((lane >> 4) << 4);

    float acc[2][4][4];
#pragma unroll
    for (int i = 0; i < 2; i++)
#pragma unroll
        for (int j = 0; j < 4; j++)
#pragma unroll
            for (int k = 0; k < 4; k++) acc[i][j][k] = 0.f;

    load_stage(0, 0); cp_commit();
    load_stage(1, 1); cp_commit();

    for (int kc = 0; kc < NKC2; kc++) {
        cp_wait<1>();
        __syncthreads();
        if (kc + 2 < NKC2) load_stage(kc + 2, (kc + 2) % NSTAGE);
        cp_commit();

        const uint32_t so = (kc % NSTAGE) * STG;
#pragma unroll
        for (int ksi = 0; ksi < 4; ksi++) {
            const uint32_t kx = ksi << 5;
            uint32_t a[2][4];
#pragma unroll
            for (int mi = 0; mi < 2; mi++)
                ldsm4(a[mi][0], a[mi][1], a[mi][2], a[mi][3],
                      (PAu ^ kx) + so + mi * 2048);
            uint32_t b[4][2];
#pragma unroll
            for (int pr = 0; pr < 2; pr++) {
                uint32_t r0, r1, r2, r3;
                ldsm4(r0, r1, r2, r3, (PBu ^ kx) + so + pr * 2048);
                b[2 * pr + 0][0] = r0; b[2 * pr + 0][1] = r2;
                b[2 * pr + 1][0] = r1; b[2 * pr + 1][1] = r3;
            }
#pragma unroll
            for (int ni = 0; ni < 4; ni++)
#pragma unroll
                for (int mi = 0; mi < 2; mi++)
                    mma16816(acc[mi][ni], a[mi], b[ni]);
        }
    }

    // epilogue: scale by routing weight, fp16 stores (half2)
#pragma unroll
    for (int mi = 0; mi < 2; mi++)
#pragma unroll
        for (int ni = 0; ni < 4; ni++)
#pragma unroll
            for (int rr = 0; rr < 2; rr++) {
                int m = wm * 32 + mi * 16 + g + rr * 8;
                if (m < rows) {
                    int col = n0 + wn * 32 + ni * 8 + 2 * t4;
                    float w = s_w[m];
                    __half2 h = __floats2half2_rn(acc[mi][ni][rr * 2 + 0] * w,
                                                  acc[mi][ni][rr * 2 + 1] * w);
                    *(__half2*)&g_down16[(size_t)(row0 + m) * HH + col] = h;
                }
            }
}

// ----------------------------------------------------------------------------
// kernel_launch — DAG: main stream carries the longest pole (cvt_ws) while
// side stream s2 runs fused_cvt_router -> scan; s3 runs cvt_w2s. Both join
// before their consumers. Creation order keeps gemm1 at index 3.
// ----------------------------------------------------------------------------
extern "C" void kernel_launch(void* const* d_in, const int* in_sizes, int n_in,
                              void* d_out, int out_size) {
    const float* hs  = (const float*)d_in[0];
    const float* rw  = (const float*)d_in[1];
    const float* ws  = (const float*)d_in[2];
    const float* w2s = (const float*)d_in[3];
    float* out = (float*)d_out;
    (void)in_sizes; (void)n_in; (void)out_size;

    static cudaStream_t s2 = nullptr, s3 = nullptr;
    static cudaEvent_t evFork = nullptr, evJ1 = nullptr, evJ2 = nullptr;
    if (!s2) {
        cudaStreamCreateWithFlags(&s2, cudaStreamNonBlocking);
        cudaStreamCreateWithFlags(&s3, cudaStreamNonBlocking);
        cudaEventCreateWithFlags(&evFork, cudaEventDisableTiming);
        cudaEventCreateWithFlags(&evJ1, cudaEventDisableTiming);
        cudaEventCreateWithFlags(&evJ2, cudaEventDisableTiming);
    }

    cudaFuncSetAttribute(gemm1_kernel,
                         cudaFuncAttributeMaxDynamicSharedMemorySize, SMEM_BYTES);
    cudaFuncSetAttribute(gemm2_kernel,
                         cudaFuncAttributeMaxDynamicSharedMemorySize, SMEM_BYTES);

    __half* hs16  = nullptr; cudaGetSymbolAddress((void**)&hs16,  g_hs16);
    __half* ws16  = nullptr; cudaGetSymbolAddress((void**)&ws16,  g_ws16);
    __half* w2s16 = nullptr; cudaGetSymbolAddress((void**)&w2s16, g_w2s16);
    __half* act   = nullptr; cudaGetSymbolAddress((void**)&act,   g_act);

    // fork side streams at graph start (all read only raw inputs)
    cudaEventRecord(evFork, 0);
    cudaStreamWaitEvent(s2, evFork, 0);
    cudaStreamWaitEvent(s3, evFork, 0);

    // 0 (main): ws fp32->fp16 — the longest pre-gemm1 pole
    cvt_kernel<<<(EE * 2 * II * (HH / 4)) / 256, 256>>>(
        (const float4*)ws, (uint2*)ws16);
    // 1 (s2): fused hidden-cvt + router
    fused_cvt_router<<<CVT_BLOCKS + RTR_BLOCKS, 256, 0, s2>>>(
        (const float4*)hs, (uint2*)hs16, (const float4*)rw);
    // 2 (s2): scan + scatter
    scan_scatter_kernel<<<1, 1024, 0, s2>>>();
    cudaEventRecord(evJ1, s2);
    cudaStreamWaitEvent(0, evJ1, 0);
    // 3 (main): gemm1  (ncu capture slot; depends on ws16 + hs16 + perm)
    dim3 g1(II / 64, MAXTILES);                  // 64 x 136
    gemm1_kernel<<<g1, NTHREADS, SMEM_BYTES>>>(hs16, ws16);
    // 4 (s3): w2s fp32->fp16 (runs from t=0, overlaps everything)
    cvt_kernel<<<(EE * HH * (II / 4)) / 256, 256, 0, s3>>>(
        (const float4*)w2s, (uint2*)w2s16);
    cudaEventRecord(evJ2, s3);
    cudaStreamWaitEvent(0, evJ2, 0);
    // 5 (main): gemm2
    dim3 g2(HH / 128, MAXTILES);                 // 16 x 136
    gemm2_kernel<<<g2, NTHREADS, SMEM_BYTES>>>(act, w2s16);
    // 6 (main): combine (8 floats per thread)
    combine_kernel<<<(TT * (HH / 8)) / 256, 256>>>(out);
}